// round 4
// baseline (speedup 1.0000x reference)
#include <cuda_runtime.h>
#include <cuda_bf16.h>
#include <cstdint>

// token_reprs: [B=32, L=512, H=768] f32 ; pos_idx: [B,E=32,M=8,S=4] i32
// out f32: entity [B,E,H] @0 ; mentions [B,E,M,H] @786432 ; mask [B,E,M] @7077888

#define B_ 32
#define L_ 512
#define H_ 768
#define E_ 32
#define M_ 8
#define S_ 4
#define HV (H_ / 4)            // 192 float4 per row
#define NROW (M_ * S_)         // 32 gathered rows per (b,e)
#define SMEM_BYTES (NROW * HV * 16)   // 96 KB landing pad

__device__ __forceinline__ void cp_async16(uint32_t saddr, const void* gaddr) {
    asm volatile("cp.async.cg.shared.global [%0], [%1], 16;\n"
                 :: "r"(saddr), "l"(gaddr));
}

__global__ __launch_bounds__(HV)
void entity_repr_kernel(const float* __restrict__ tok,
                        const int* __restrict__ pos,
                        float* __restrict__ ent,
                        float* __restrict__ men,
                        float* __restrict__ mask)
{
    extern __shared__ float4 sbuf[];        // [NROW][HV], thread t owns column t
    __shared__ int sidx[NROW];

    const int be = blockIdx.x;              // 0 .. B*E-1
    const int b  = be >> 5;                 // E_ == 32
    const int t  = threadIdx.x;             // float4 column 0..191

    if (t < NROW) {
        sidx[t] = pos[(size_t)be * NROW + t];
    }
    __syncthreads();

    const float4* __restrict__ tokb =
        reinterpret_cast<const float4*>(tok) + (size_t)b * L_ * HV;

    // Per-thread smem column base (16B slots strided by row)
    uint32_t scol = (uint32_t)__cvta_generic_to_shared(&sbuf[t]);

    // Group 0: rows 0..15 (mentions 0..3)
    #pragma unroll
    for (int r = 0; r < 16; r++) {
        cp_async16(scol + (uint32_t)r * (HV * 16), &tokb[(size_t)sidx[r] * HV + t]);
    }
    asm volatile("cp.async.commit_group;\n" ::: "memory");

    // Group 1: rows 16..31 (mentions 4..7)
    #pragma unroll
    for (int r = 16; r < 32; r++) {
        cp_async16(scol + (uint32_t)r * (HV * 16), &tokb[(size_t)sidx[r] * HV + t]);
    }
    asm volatile("cp.async.commit_group;\n" ::: "memory");

    float4* __restrict__ men4 =
        reinterpret_cast<float4*>(men) + ((size_t)be * M_) * HV;
    float4* __restrict__ ent4 =
        reinterpret_cast<float4*>(ent) + (size_t)be * HV;

    float ex = 0.f, ey = 0.f, ez = 0.f, ew = 0.f;

    // Wait for group 0 only (group 1 still in flight while we compute)
    asm volatile("cp.async.wait_group 1;\n" ::: "memory");

    #pragma unroll
    for (int m = 0; m < 4; m++) {
        const float4 v0 = sbuf[(m * S_ + 0) * HV + t];
        const float4 v1 = sbuf[(m * S_ + 1) * HV + t];
        const float4 v2 = sbuf[(m * S_ + 2) * HV + t];
        const float4 v3 = sbuf[(m * S_ + 3) * HV + t];
        float4 r;
        r.x = (v0.x + v1.x + v2.x + v3.x) * 0.25f;
        r.y = (v0.y + v1.y + v2.y + v3.y) * 0.25f;
        r.z = (v0.z + v1.z + v2.z + v3.z) * 0.25f;
        r.w = (v0.w + v1.w + v2.w + v3.w) * 0.25f;
        __stcs(&men4[(size_t)m * HV + t], r);
        ex += r.x; ey += r.y; ez += r.z; ew += r.w;
    }

    // Wait for group 1
    asm volatile("cp.async.wait_group 0;\n" ::: "memory");

    #pragma unroll
    for (int m = 4; m < M_; m++) {
        const float4 v0 = sbuf[(m * S_ + 0) * HV + t];
        const float4 v1 = sbuf[(m * S_ + 1) * HV + t];
        const float4 v2 = sbuf[(m * S_ + 2) * HV + t];
        const float4 v3 = sbuf[(m * S_ + 3) * HV + t];
        float4 r;
        r.x = (v0.x + v1.x + v2.x + v3.x) * 0.25f;
        r.y = (v0.y + v1.y + v2.y + v3.y) * 0.25f;
        r.z = (v0.z + v1.z + v2.z + v3.z) * 0.25f;
        r.w = (v0.w + v1.w + v2.w + v3.w) * 0.25f;
        __stcs(&men4[(size_t)m * HV + t], r);
        ex += r.x; ey += r.y; ez += r.z; ew += r.w;
    }

    float4 er;
    er.x = ex * 0.125f; er.y = ey * 0.125f;
    er.z = ez * 0.125f; er.w = ew * 0.125f;
    __stcs(&ent4[t], er);

    if (t < M_) {
        mask[(size_t)be * M_ + t] = 1.0f;
    }
}

extern "C" void kernel_launch(void* const* d_in, const int* in_sizes, int n_in,
                              void* d_out, int out_size)
{
    const float* tok = (const float*)d_in[0];
    const int*   pos = (const int*)d_in[1];

    float* out = (float*)d_out;
    float* ent  = out;                                  // 786432
    float* men  = out + (size_t)B_ * E_ * H_;           // +786432
    float* mask = men + (size_t)B_ * E_ * M_ * H_;      // +6291456

    static int configured = 0;
    if (!configured) {
        cudaFuncSetAttribute(entity_repr_kernel,
                             cudaFuncAttributeMaxDynamicSharedMemorySize,
                             SMEM_BYTES);
        configured = 1;
    }

    entity_repr_kernel<<<B_ * E_, HV, SMEM_BYTES>>>(tok, pos, ent, men, mask);
}

// round 6
// speedup vs baseline: 1.1210x; 1.1210x over previous
#include <cuda_runtime.h>
#include <cuda_bf16.h>
#include <cstdint>

// token_reprs: [B=32, L=512, H=768] f32 ; pos_idx: [B,E=32,M=8,S=4] i32
// out f32: entity [B,E,H] @0 ; mentions [B,E,M,H] @786432 ; mask [B,E,M] @7077888

#define B_ 32
#define L_ 512
#define H_ 768
#define E_ 32
#define M_ 8
#define S_ 4
#define HV (H_ / 4)            // 192 float4 per row
#define NROW (M_ * S_)         // 32 gathered rows per (b,e)

__device__ __forceinline__ void cp_async16(uint32_t saddr, const void* gaddr) {
    asm volatile("cp.async.cg.shared.global [%0], [%1], 16;\n"
                 :: "r"(saddr), "l"(gaddr));
}
__device__ __forceinline__ void cp_commit() {
    asm volatile("cp.async.commit_group;\n" ::: "memory");
}
template <int N>
__device__ __forceinline__ void cp_wait() {
    asm volatile("cp.async.wait_group %0;\n" :: "n"(N) : "memory");
}

// Ring: 2 mention-buffers x 4 rows x 192 float4 = 24 KB -> 8 blocks/SM, single wave.
__global__ __launch_bounds__(HV, 8)
void entity_repr_kernel(const float* __restrict__ tok,
                        const int* __restrict__ pos,
                        float* __restrict__ ent,
                        float* __restrict__ men,
                        float* __restrict__ mask)
{
    __shared__ float4 sbuf[2][S_][HV];   // thread t owns column t in every row
    __shared__ int sidx[NROW];

    const int be = blockIdx.x;           // 0 .. B*E-1
    const int b  = be >> 5;              // E_ == 32
    const int t  = threadIdx.x;          // float4 column 0..191

    if (t < NROW) {
        sidx[t] = pos[(size_t)be * NROW + t];
    }
    __syncthreads();

    const float4* __restrict__ tokb =
        reinterpret_cast<const float4*>(tok) + (size_t)b * L_ * HV;

    const uint32_t scol0 = (uint32_t)__cvta_generic_to_shared(&sbuf[0][0][t]);
    const uint32_t scol1 = (uint32_t)__cvta_generic_to_shared(&sbuf[1][0][t]);
    const uint32_t rowstride = HV * 16;  // bytes between rows in a buffer

    // Prologue: mentions 0 and 1 in flight
    #pragma unroll
    for (int s = 0; s < S_; s++)
        cp_async16(scol0 + s * rowstride, &tokb[(size_t)sidx[0 * S_ + s] * HV + t]);
    cp_commit();
    #pragma unroll
    for (int s = 0; s < S_; s++)
        cp_async16(scol1 + s * rowstride, &tokb[(size_t)sidx[1 * S_ + s] * HV + t]);
    cp_commit();

    float4* __restrict__ men4 =
        reinterpret_cast<float4*>(men) + ((size_t)be * M_) * HV;
    float4* __restrict__ ent4 =
        reinterpret_cast<float4*>(ent) + (size_t)be * HV;

    float ex = 0.f, ey = 0.f, ez = 0.f, ew = 0.f;

    #pragma unroll
    for (int m = 0; m < M_; m++) {
        // Pending groups here: {m} for the last iteration, {m, m+1} otherwise.
        // Must fully drain on the last iteration (this was the R4 bug).
        if (m == M_ - 1) cp_wait<0>();
        else             cp_wait<1>();

        const int buf = m & 1;
        const float4 v0 = sbuf[buf][0][t];
        const float4 v1 = sbuf[buf][1][t];
        const float4 v2 = sbuf[buf][2][t];
        const float4 v3 = sbuf[buf][3][t];

        float4 r;
        r.x = (v0.x + v1.x + v2.x + v3.x) * 0.25f;
        r.y = (v0.y + v1.y + v2.y + v3.y) * 0.25f;
        r.z = (v0.z + v1.z + v2.z + v3.z) * 0.25f;
        r.w = (v0.w + v1.w + v2.w + v3.w) * 0.25f;

        __stcs(&men4[(size_t)m * HV + t], r);
        ex += r.x; ey += r.y; ez += r.z; ew += r.w;

        // Refill the just-consumed buffer with mention m+2.
        // Safe: the LDS above (29 cyc) completes long before cp.async's
        // global data (~300+ cyc) can land in the same slots.
        if (m + 2 < M_) {
            const uint32_t scol = buf ? scol1 : scol0;
            #pragma unroll
            for (int s = 0; s < S_; s++)
                cp_async16(scol + s * rowstride,
                           &tokb[(size_t)sidx[(m + 2) * S_ + s] * HV + t]);
            cp_commit();
        }
    }

    float4 er;
    er.x = ex * 0.125f; er.y = ey * 0.125f;
    er.z = ez * 0.125f; er.w = ew * 0.125f;
    __stcs(&ent4[t], er);

    if (t < M_) {
        mask[(size_t)be * M_ + t] = 1.0f;
    }
}

extern "C" void kernel_launch(void* const* d_in, const int* in_sizes, int n_in,
                              void* d_out, int out_size)
{
    const float* tok = (const float*)d_in[0];
    const int*   pos = (const int*)d_in[1];

    float* out = (float*)d_out;
    float* ent  = out;                                  // 786432
    float* men  = out + (size_t)B_ * E_ * H_;           // +786432
    float* mask = men + (size_t)B_ * E_ * M_ * H_;      // +6291456

    entity_repr_kernel<<<B_ * E_, HV>>>(tok, pos, ent, men, mask);
}